// round 10
// baseline (speedup 1.0000x reference)
#include <cuda_runtime.h>
#include <cstdint>

// Unpool (stride-2 zero insertion):
//   in : (8, 256, 112, 112) fp32 -> out: (8, 256, 224, 224) fp32
//   out[..., ::2, ::2] = in, else 0.
//
// Traffic is hardware-pinned at ~455MB/replay (411MB writes + 44MB read
// misses); every cache-policy mechanism available on sm_103a has been tried
// and is neutral. Bench pins at 455MB / ~5.7TB/s sustained = 79.8us.
// This round isolates R7's regression cause: 2 v8-chunks per thread (64B
// read, 256B written) but at 256-thread blocks (R7 used 512 -> occ 58.5%).
// Row = 14 chunks, so pair (2k,2k+1) never straddles rows: irow = idx/7.

namespace {
constexpr int W4_OUT = 56;   // float4 per 224-wide output row
}

__device__ __forceinline__ void ldg256_evict_last(const void* p, float* v)
{
    asm volatile("ld.global.L2::evict_last.v8.f32 {%0,%1,%2,%3,%4,%5,%6,%7}, [%8];"
                 : "=f"(v[0]), "=f"(v[1]), "=f"(v[2]), "=f"(v[3]),
                   "=f"(v[4]), "=f"(v[5]), "=f"(v[6]), "=f"(v[7])
                 : "l"(p));
}

__device__ __forceinline__ void stg256_cs(void* p,
                                          float v0, float v1, float v2, float v3,
                                          float v4, float v5, float v6, float v7)
{
    asm volatile(
        "st.global.cs.v8.f32 [%0], {%1,%2,%3,%4,%5,%6,%7,%8};"
        :: "l"(p),
           "f"(v0), "f"(v1), "f"(v2), "f"(v3),
           "f"(v4), "f"(v5), "f"(v6), "f"(v7)
        : "memory");
}

__global__ void __launch_bounds__(256)
unpool_kernel(const float* __restrict__ x,
              float4* __restrict__ out,
              int total)              // total = global_input_rows * 7
{
    int idx = blockIdx.x * blockDim.x + threadIdx.x;
    if (idx >= total) return;

    int irow = idx / 7;               // global input row (img*112 + ih)
    int c0   = 2 * (idx - irow * 7);  // first v8 chunk (0,2,...,12)

    // two independent 256-bit loads, back-to-back (MLP=2)
    float a[8], b[8];
    const float* src = x + (size_t)irow * 112 + c0 * 8;
    ldg256_evict_last(src,     a);
    ldg256_evict_last(src + 8, b);

    float4* even = out + (size_t)(2 * irow)     * W4_OUT + 4 * c0;
    float4* odd  = out + (size_t)(2 * irow + 1) * W4_OUT + 4 * c0;

    stg256_cs(even,     a[0], 0.f, a[1], 0.f, a[2], 0.f, a[3], 0.f);
    stg256_cs(even + 2, a[4], 0.f, a[5], 0.f, a[6], 0.f, a[7], 0.f);
    stg256_cs(even + 4, b[0], 0.f, b[1], 0.f, b[2], 0.f, b[3], 0.f);
    stg256_cs(even + 6, b[4], 0.f, b[5], 0.f, b[6], 0.f, b[7], 0.f);
    stg256_cs(odd,      0.f, 0.f, 0.f, 0.f, 0.f, 0.f, 0.f, 0.f);
    stg256_cs(odd + 2,  0.f, 0.f, 0.f, 0.f, 0.f, 0.f, 0.f, 0.f);
    stg256_cs(odd + 4,  0.f, 0.f, 0.f, 0.f, 0.f, 0.f, 0.f, 0.f);
    stg256_cs(odd + 6,  0.f, 0.f, 0.f, 0.f, 0.f, 0.f, 0.f, 0.f);
}

extern "C" void kernel_launch(void* const* d_in, const int* in_sizes, int n_in,
                              void* d_out, int out_size)
{
    const float* x = (const float*)d_in[0];
    float4* out = (float4*)d_out;

    // out_size = B*C*224*224 floats. Threads = input floats / 16 = out_size / 64.
    int total = out_size / 64;

    const int threads = 256;
    int blocks = (total + threads - 1) / threads;
    unpool_kernel<<<blocks, threads>>>(x, out, total);
}

// round 11
// speedup vs baseline: 1.0444x; 1.0444x over previous
#include <cuda_runtime.h>
#include <cstdint>

// Unpool (stride-2 zero insertion):
//   in : (8, 256, 112, 112) fp32 -> out: (8, 256, 224, 224) fp32
//   out[..., ::2, ::2] = in, else 0.
//
// Final config after 10 rounds of measurement:
//  - Traffic is HW-pinned at ~455MB/replay (411MB writes irreducible; 44MB
//    input read misses immune to .cs/.wt/evict_last/createpolicy — all tried).
//  - Bench pins at 455MB / ~5.7TB/s sustained = ~79.8us; ncu single-capture
//    sees ~75us at boost clocks.
//  - SM-optimal shape (proven vs 2-chunk/512t and 2-chunk/256t variants):
//    one v8 chunk (32B) per thread, 256-thread blocks, four 256-bit stores.
//  - Micro-opt: the two zero stores have no data dependency -> issue them
//    BEFORE the load so they drain during the load-miss window; the two
//    data stores follow the load.

namespace {
constexpr int W8_IN  = 14;   // 8-float chunks per 112-wide input row
constexpr int W4_OUT = 56;   // float4 per 224-wide output row
}

__device__ __forceinline__ void ldg256_evict_last(const void* p, float* v)
{
    asm volatile("ld.global.L2::evict_last.v8.f32 {%0,%1,%2,%3,%4,%5,%6,%7}, [%8];"
                 : "=f"(v[0]), "=f"(v[1]), "=f"(v[2]), "=f"(v[3]),
                   "=f"(v[4]), "=f"(v[5]), "=f"(v[6]), "=f"(v[7])
                 : "l"(p));
}

__device__ __forceinline__ void stg256_cs(void* p,
                                          float v0, float v1, float v2, float v3,
                                          float v4, float v5, float v6, float v7)
{
    asm volatile(
        "st.global.cs.v8.f32 [%0], {%1,%2,%3,%4,%5,%6,%7,%8};"
        :: "l"(p),
           "f"(v0), "f"(v1), "f"(v2), "f"(v3),
           "f"(v4), "f"(v5), "f"(v6), "f"(v7)
        : "memory");
}

__global__ void __launch_bounds__(256)
unpool_kernel(const float* __restrict__ x,
              float4* __restrict__ out,
              int total)              // total = global_input_rows * 14
{
    int idx = blockIdx.x * blockDim.x + threadIdx.x;
    if (idx >= total) return;

    int irow = idx / W8_IN;           // global input row (img*112 + ih)
    int c    = idx - irow * W8_IN;    // v8 chunk column in input row

    float4* even = out + (size_t)(2 * irow)     * W4_OUT + 4 * c;
    float4* odd  = out + (size_t)(2 * irow + 1) * W4_OUT + 4 * c;

    // independent zero stores first: drain during the load-miss window
    stg256_cs(odd,      0.f, 0.f, 0.f, 0.f, 0.f, 0.f, 0.f, 0.f);
    stg256_cs(odd + 2,  0.f, 0.f, 0.f, 0.f, 0.f, 0.f, 0.f, 0.f);

    float a[8];
    ldg256_evict_last(x + (size_t)irow * 112 + c * 8, a);

    stg256_cs(even,     a[0], 0.f, a[1], 0.f, a[2], 0.f, a[3], 0.f);
    stg256_cs(even + 2, a[4], 0.f, a[5], 0.f, a[6], 0.f, a[7], 0.f);
}

extern "C" void kernel_launch(void* const* d_in, const int* in_sizes, int n_in,
                              void* d_out, int out_size)
{
    const float* x = (const float*)d_in[0];
    float4* out = (float4*)d_out;

    // out_size = B*C*224*224 floats. Threads = input floats / 8 = out_size / 32.
    int total = out_size / 32;

    const int threads = 256;
    int blocks = (total + threads - 1) / threads;
    unpool_kernel<<<blocks, threads>>>(x, out, total);
}

// round 12
// speedup vs baseline: 1.0453x; 1.0008x over previous
#include <cuda_runtime.h>
#include <cstdint>

// Unpool (stride-2 zero insertion):
//   in : (8, 256, 112, 112) fp32 -> out: (8, 256, 224, 224) fp32
//   out[..., ::2, ::2] = in, else 0.
//
// Floor model (confirmed over 11 rounds): traffic HW-pinned at ~455MB/replay
// (411MB writes + 44MB read misses immune to every cache policy); bench pins
// at 455MB / ~5.7TB/s sustained = 79.8-80.0us for every SM-efficient shape.
// Last lever: DRAM bus-turnaround separation. Two kernels in one capture:
//   1) zero_kernel: pure write stream (all odd output rows, 205MB, 0 reads)
//   2) copy_kernel: even rows (205MB writes + reads)
// Same total traffic; the pure-write phase eliminates read/write turnaround
// cycles at the HBM controller for half the volume.

namespace {
constexpr int W8_IN  = 14;   // 8-float chunks per 112-wide input row
constexpr int W4_OUT = 56;   // float4 per 224-wide output row
}

__device__ __forceinline__ void ldg256_evict_last(const void* p, float* v)
{
    asm volatile("ld.global.L2::evict_last.v8.f32 {%0,%1,%2,%3,%4,%5,%6,%7}, [%8];"
                 : "=f"(v[0]), "=f"(v[1]), "=f"(v[2]), "=f"(v[3]),
                   "=f"(v[4]), "=f"(v[5]), "=f"(v[6]), "=f"(v[7])
                 : "l"(p));
}

__device__ __forceinline__ void stg256_cs(void* p,
                                          float v0, float v1, float v2, float v3,
                                          float v4, float v5, float v6, float v7)
{
    asm volatile(
        "st.global.cs.v8.f32 [%0], {%1,%2,%3,%4,%5,%6,%7,%8};"
        :: "l"(p),
           "f"(v0), "f"(v1), "f"(v2), "f"(v3),
           "f"(v4), "f"(v5), "f"(v6), "f"(v7)
        : "memory");
}

// Kernel 1: pure write stream — zero all odd output rows.
// One thread per (input row, v8 chunk): two 256-bit zero stores (64B).
__global__ void __launch_bounds__(256)
zero_kernel(float4* __restrict__ out, int total)   // total = rows * 14
{
    int idx = blockIdx.x * blockDim.x + threadIdx.x;
    if (idx >= total) return;

    int irow = idx / W8_IN;
    int c    = idx - irow * W8_IN;

    float4* odd = out + (size_t)(2 * irow + 1) * W4_OUT + 4 * c;
    stg256_cs(odd,     0.f, 0.f, 0.f, 0.f, 0.f, 0.f, 0.f, 0.f);
    stg256_cs(odd + 2, 0.f, 0.f, 0.f, 0.f, 0.f, 0.f, 0.f, 0.f);
}

// Kernel 2: even rows — one v8 load (32B), two 256-bit interleaved stores (64B).
__global__ void __launch_bounds__(256)
copy_kernel(const float* __restrict__ x,
            float4* __restrict__ out, int total)   // total = rows * 14
{
    int idx = blockIdx.x * blockDim.x + threadIdx.x;
    if (idx >= total) return;

    int irow = idx / W8_IN;
    int c    = idx - irow * W8_IN;

    float a[8];
    ldg256_evict_last(x + (size_t)irow * 112 + c * 8, a);

    float4* even = out + (size_t)(2 * irow) * W4_OUT + 4 * c;
    stg256_cs(even,     a[0], 0.f, a[1], 0.f, a[2], 0.f, a[3], 0.f);
    stg256_cs(even + 2, a[4], 0.f, a[5], 0.f, a[6], 0.f, a[7], 0.f);
}

extern "C" void kernel_launch(void* const* d_in, const int* in_sizes, int n_in,
                              void* d_out, int out_size)
{
    const float* x = (const float*)d_in[0];
    float4* out = (float4*)d_out;

    // out_size = B*C*224*224 floats. Chunks = input floats / 8 = out_size / 32.
    int total = out_size / 32;

    const int threads = 256;
    int blocks = (total + threads - 1) / threads;

    zero_kernel<<<blocks, threads>>>(out, total);
    copy_kernel<<<blocks, threads>>>(x, out, total);
}